// round 11
// baseline (speedup 1.0000x reference)
#include <cuda_runtime.h>
#include <cuda_fp16.h>
#include <math.h>
#include <stdint.h>

#define D_MODEL 1024
#define NHEAD   16
#define HDIM    64
#define FFH     2048
#define BATCH   4
#define SEQ     2048
#define NTOK    (BATCH * SEQ)   // 8192

// ---------------- scratch (alloc-free: __device__ globals) ----------------
__device__ __half g_h[NTOK * D_MODEL];
__device__ __half g_qkv[NTOK * 3 * D_MODEL];
__device__ __half g_ctx[NTOK * D_MODEL];
__device__ float  g_x1[NTOK * D_MODEL];
__device__ __half g_ffh[NTOK * FFH];
// pre-converted transposed weights  Wt[n][k] = fp16(W[k][n])
__device__ __half g_wq[3 * D_MODEL * D_MODEL];
__device__ __half g_wo[D_MODEL * D_MODEL];
__device__ __half g_w1[FFH * D_MODEL];
__device__ __half g_w2[D_MODEL * FFH];

// ======================= helpers =======================
__device__ __forceinline__ uint32_t smem_u32(const void* p) {
    uint32_t a;
    asm("{ .reg .u64 t; cvta.to.shared.u64 t, %1; cvt.u32.u64 %0, t; }" : "=r"(a) : "l"(p));
    return a;
}
__device__ __forceinline__ void cp16(uint32_t d, const void* s) {
    asm volatile("cp.async.cg.shared.global [%0], [%1], 16;" :: "r"(d), "l"(s));
}
__device__ __forceinline__ void cp_commit() {
    asm volatile("cp.async.commit_group;");
}
template <int N>
__device__ __forceinline__ void cp_wait() {
    asm volatile("cp.async.wait_group %0;" :: "n"(N));
}
__device__ __forceinline__ void ldmx4(uint32_t& r0, uint32_t& r1, uint32_t& r2, uint32_t& r3,
                                      uint32_t addr) {
    asm volatile("ldmatrix.sync.aligned.m8n8.x4.shared.b16 {%0,%1,%2,%3}, [%4];"
                 : "=r"(r0), "=r"(r1), "=r"(r2), "=r"(r3) : "r"(addr));
}
__device__ __forceinline__ void ldmx4t(uint32_t& r0, uint32_t& r1, uint32_t& r2, uint32_t& r3,
                                       uint32_t addr) {
    asm volatile("ldmatrix.sync.aligned.m8n8.x4.trans.shared.b16 {%0,%1,%2,%3}, [%4];"
                 : "=r"(r0), "=r"(r1), "=r"(r2), "=r"(r3) : "r"(addr));
}
__device__ __forceinline__ void mma_f16(float* d, const uint32_t* a, const uint32_t* b) {
    asm volatile(
        "mma.sync.aligned.m16n8k16.row.col.f32.f16.f16.f32 "
        "{%0,%1,%2,%3},{%4,%5,%6,%7},{%8,%9},{%0,%1,%2,%3};"
        : "+f"(d[0]), "+f"(d[1]), "+f"(d[2]), "+f"(d[3])
        : "r"(a[0]), "r"(a[1]), "r"(a[2]), "r"(a[3]), "r"(b[0]), "r"(b[1]));
}
__device__ __forceinline__ uint32_t pack2h(float a, float b) {
    __half2 h = __halves2half2(__float2half_rn(a), __float2half_rn(b));
    return *reinterpret_cast<uint32_t*>(&h);
}
__device__ __forceinline__ float gelu_exact(float v) {
    return 0.5f * v * (1.0f + erff(v * 0.70710678118654752f));
}

// ======================= weight transpose + fp16 convert =======================
__global__ __launch_bounds__(256) void wconv(const float* __restrict__ W,
                                             __half* __restrict__ Wh,
                                             int N, int K) {
    __shared__ float t[32][33];
    int n0 = blockIdx.x * 32, k0 = blockIdx.y * 32;
    int tx = threadIdx.x & 31, ty = threadIdx.x >> 5;
    #pragma unroll
    for (int i = ty; i < 32; i += 8)
        t[i][tx] = W[(size_t)(k0 + i) * N + n0 + tx];
    __syncthreads();
    #pragma unroll
    for (int i = ty; i < 32; i += 8)
        Wh[(size_t)(n0 + i) * K + k0 + tx] = __float2half_rn(t[tx][i]);
}

// ======================= HMMA fp16 GEMM =======================
// C = A @ Wt^T + bias (+gelu)(+res); A fp16 [M][K], Wt fp16 [N][K].
// CTA 128x128, BK=64, 512 thr (warp 32x32), 3-stage single-sync pipeline.
#define TPITCH 144
#define TILE_B (128 * TPITCH)          // 18432
#define BUF_B  (2 * TILE_B)            // 36864 (A, B)
#define NSTAGE 3
#define GEMM_SMEM (NSTAGE * BUF_B)     // 110592

template <bool GELU, bool RES, bool OHALF>
__global__ __launch_bounds__(512, 1) void hmma_gemm(const __half* __restrict__ A,
                                                    const __half* __restrict__ Bt,
                                                    const float* __restrict__ bias,
                                                    const float* __restrict__ R,
                                                    float* __restrict__ C,
                                                    __half* __restrict__ Oh,
                                                    int M, int N, int K) {
    extern __shared__ char smem[];
    const uint32_t sb = smem_u32(smem);
    const int tid = threadIdx.x;
    const int lane = tid & 31;
    const int wid = tid >> 5;
    const int wm = wid & 3;
    const int wn = wid >> 2;
    const int m0 = blockIdx.y * 128, n0 = blockIdx.x * 128;

    const int srow = tid >> 2;                 // 0..127
    const int spos = (tid & 3) * 16;           // element offset 0/16/32/48
    const uint32_t sdst = (uint32_t)(srow * TPITCH + spos * 2);

    float acc[2][4][4];
    #pragma unroll
    for (int i = 0; i < 2; i++)
        #pragma unroll
        for (int j = 0; j < 4; j++)
            #pragma unroll
            for (int l = 0; l < 4; l++) acc[i][j][l] = 0.f;

    const int nch = K >> 6;   // BK=64

    auto stage = [&](int c, int buf) {
        const int k0 = (c << 6) + spos;
        uint32_t d = sb + buf * BUF_B + sdst;
        const size_t ao = (size_t)(m0 + srow) * K + k0;
        const size_t bo = (size_t)(n0 + srow) * K + k0;
        cp16(d,               A  + ao);
        cp16(d + 16,          A  + ao + 8);
        cp16(d + TILE_B,      Bt + bo);
        cp16(d + TILE_B + 16, Bt + bo + 8);
        cp_commit();
    };

    stage(0, 0);
    if (nch > 1) stage(1, 1);

    for (int c = 0; c < nch; c++) {
        if (c + 1 < nch) cp_wait<1>(); else cp_wait<0>();
        __syncthreads();
        if (c + 2 < nch) stage(c + 2, (c + 2) % NSTAGE);

        const uint32_t bufb = sb + (c % NSTAGE) * BUF_B;
        const uint32_t lrow = (lane & 15);
        const uint32_t lseg = (lane >> 4) << 4;
        #pragma unroll
        for (int ks = 0; ks < 4; ks++) {
            const uint32_t kb = ks * 32;
            uint32_t af[2][4], b4[2][4];
            #pragma unroll
            for (int mt = 0; mt < 2; mt++) {
                uint32_t ar = (uint32_t)((wm * 32 + mt * 16 + lrow) * TPITCH) + kb + lseg;
                ldmx4(af[mt][0], af[mt][1], af[mt][2], af[mt][3], bufb + ar);
            }
            #pragma unroll
            for (int np = 0; np < 2; np++) {
                uint32_t br = (uint32_t)((wn * 32 + np * 16 + lrow) * TPITCH) + kb + lseg;
                ldmx4(b4[np][0], b4[np][1], b4[np][2], b4[np][3], bufb + TILE_B + br);
            }
            #pragma unroll
            for (int nt = 0; nt < 4; nt++) {
                const int np = nt >> 1, sel = nt & 1;
                uint32_t bf[2] = {b4[np][sel], b4[np][sel + 2]};
                #pragma unroll
                for (int mt = 0; mt < 2; mt++)
                    mma_f16(acc[mt][nt], af[mt], bf);
            }
        }
    }

    // ---- epilogue ----
    #pragma unroll
    for (int mt = 0; mt < 2; mt++) {
        #pragma unroll
        for (int nt = 0; nt < 4; nt++) {
            int col = n0 + wn * 32 + nt * 8 + (lane & 3) * 2;
            float b0 = bias[col], b1 = bias[col + 1];
            #pragma unroll
            for (int half = 0; half < 2; half++) {
                int row = m0 + wm * 32 + mt * 16 + (lane >> 2) + half * 8;
                float o0 = acc[mt][nt][half * 2 + 0] + b0;
                float o1 = acc[mt][nt][half * 2 + 1] + b1;
                if (GELU) { o0 = gelu_exact(o0); o1 = gelu_exact(o1); }
                if (RES) {
                    const float* rp = R + (size_t)row * N + col;
                    o0 += rp[0]; o1 += rp[1];
                }
                if (OHALF) {
                    *(uint32_t*)(Oh + (size_t)row * N + col) = pack2h(o0, o1);
                } else {
                    *(float2*)(C + (size_t)row * N + col) = make_float2(o0, o1);
                }
            }
        }
    }
}

// ======================= HMMA fp16 flash attention =======================
// Q [128][64] static; K,V triple-buffered cp.async, single sync per tile;
// V loaded with ldmatrix.trans.
#define AP 144
#define AQ 0                            // 128*144 = 18432
#define AKB(b) (18432 + (b) * 9216)     // 3 K buffers: 18432..46080
#define AVB(b) (46080 + (b) * 9216)     // 3 V buffers: 46080..73728
#define ATT_SMEM 73728

__global__ __launch_bounds__(256, 2) void attn_hmma(const __half* __restrict__ qkv,
                                                    __half* __restrict__ ctx) {
    extern __shared__ char sm[];
    const uint32_t sb = smem_u32(sm);
    const int tid = threadIdx.x;
    const int lane = tid & 31;
    const int wid = tid >> 5;
    const int b = blockIdx.z, h = blockIdx.y;
    const int q0 = blockIdx.x * 128;

    // ---- stage Q [128][64] (plain copies; visible after first barrier) ----
    {
        const size_t qbase = ((size_t)(b * SEQ + q0)) * (3 * D_MODEL) + h * HDIM;
        #pragma unroll
        for (int rep = 0; rep < 4; rep++) {
            int idx = rep * 256 + tid;
            int row = idx >> 3;
            int seg = idx & 7;
            size_t src = qbase + (size_t)row * (3 * D_MODEL) + seg * 8;
            *(uint4*)(sm + AQ + row * AP + seg * 16) = *(const uint4*)(qkv + src);
        }
    }

    auto stage_kv = [&](int kt, int buf) {
        const size_t kbase = ((size_t)(b * SEQ + kt)) * (3 * D_MODEL) + D_MODEL + h * HDIM;
        #pragma unroll
        for (int rep = 0; rep < 2; rep++) {
            int idx = rep * 256 + tid;
            int row = idx >> 3;
            int seg = idx & 7;
            size_t src = kbase + (size_t)row * (3 * D_MODEL) + seg * 8;
            uint32_t dst = (uint32_t)(row * AP + seg * 16);
            cp16(sb + AKB(buf) + dst, qkv + src);
            cp16(sb + AVB(buf) + dst, qkv + src + D_MODEL);
        }
        cp_commit();
    };

    float acc[8][4];
    #pragma unroll
    for (int i = 0; i < 8; i++)
        #pragma unroll
        for (int j = 0; j < 4; j++) acc[i][j] = 0.f;
    float mrow0 = -1e30f, mrow1 = -1e30f;
    float lrow0 = 0.f, lrow1 = 0.f;

    const int NT = SEQ / 64;   // 32
    stage_kv(0, 0);
    stage_kv(64, 1);

    for (int it = 0; it < NT; it++) {
        if (it + 1 < NT) cp_wait<1>(); else cp_wait<0>();
        __syncthreads();
        if (it + 2 < NT) stage_kv((it + 2) * 64, (it + 2) % 3);

        const uint32_t kbb = sb + AKB(it % 3);
        const uint32_t vbb = sb + AVB(it % 3);

        // ---- S = Q @ K^T ----
        float sf[8][4];
        #pragma unroll
        for (int i = 0; i < 8; i++)
            #pragma unroll
            for (int j = 0; j < 4; j++) sf[i][j] = 0.f;

        #pragma unroll
        for (int ks = 0; ks < 4; ks++) {
            uint32_t qaddr = sb + AQ + (uint32_t)((wid * 16 + (lane & 15)) * AP)
                           + ks * 32 + ((lane >> 4) << 4);
            uint32_t qf[4];
            ldmx4(qf[0], qf[1], qf[2], qf[3], qaddr);
            #pragma unroll
            for (int np = 0; np < 4; np++) {
                uint32_t kaddr = kbb + (uint32_t)((np * 16 + (lane & 15)) * AP)
                               + ks * 32 + ((lane >> 4) << 4);
                uint32_t kf[4];
                ldmx4(kf[0], kf[1], kf[2], kf[3], kaddr);
                uint32_t bh0[2] = {kf[0], kf[2]}, bh1[2] = {kf[1], kf[3]};
                mma_f16(sf[2 * np + 0], qf, bh0);
                mma_f16(sf[2 * np + 1], qf, bh1);
            }
        }
        #pragma unroll
        for (int nt = 0; nt < 8; nt++)
            #pragma unroll
            for (int j = 0; j < 4; j++) sf[nt][j] *= 0.125f;

        // ---- online softmax ----
        float tm0 = -1e30f, tm1 = -1e30f;
        #pragma unroll
        for (int nt = 0; nt < 8; nt++) {
            tm0 = fmaxf(tm0, fmaxf(sf[nt][0], sf[nt][1]));
            tm1 = fmaxf(tm1, fmaxf(sf[nt][2], sf[nt][3]));
        }
        #pragma unroll
        for (int o = 1; o < 4; o <<= 1) {
            tm0 = fmaxf(tm0, __shfl_xor_sync(0xffffffffu, tm0, o));
            tm1 = fmaxf(tm1, __shfl_xor_sync(0xffffffffu, tm1, o));
        }
        float mn0 = fmaxf(mrow0, tm0), mn1 = fmaxf(mrow1, tm1);
        float f0 = __expf(mrow0 - mn0), f1 = __expf(mrow1 - mn1);
        mrow0 = mn0; mrow1 = mn1;
        lrow0 *= f0; lrow1 *= f1;
        #pragma unroll
        for (int dt = 0; dt < 8; dt++) {
            acc[dt][0] *= f0; acc[dt][1] *= f0;
            acc[dt][2] *= f1; acc[dt][3] *= f1;
        }
        #pragma unroll
        for (int nt = 0; nt < 8; nt++) {
            sf[nt][0] = __expf(sf[nt][0] - mn0);
            sf[nt][1] = __expf(sf[nt][1] - mn0);
            sf[nt][2] = __expf(sf[nt][2] - mn1);
            sf[nt][3] = __expf(sf[nt][3] - mn1);
            lrow0 += sf[nt][0] + sf[nt][1];
            lrow1 += sf[nt][2] + sf[nt][3];
        }

        // ---- ctx += P @ V  (V in [key][d] layout, trans ldmatrix) ----
        #pragma unroll
        for (int ks = 0; ks < 4; ks++) {
            int nt0 = 2 * ks, nt1 = 2 * ks + 1;
            uint32_t pf[4];
            pf[0] = pack2h(sf[nt0][0], sf[nt0][1]);
            pf[1] = pack2h(sf[nt0][2], sf[nt0][3]);
            pf[2] = pack2h(sf[nt1][0], sf[nt1][1]);
            pf[3] = pack2h(sf[nt1][2], sf[nt1][3]);
            #pragma unroll
            for (int dp = 0; dp < 4; dp++) {
                uint32_t vaddr = vbb + (uint32_t)((ks * 16 + (lane & 15)) * AP)
                               + dp * 32 + ((lane >> 4) << 4);
                uint32_t r0, r1, r2, r3;
                ldmx4t(r0, r1, r2, r3, vaddr);
                uint32_t bh0[2] = {r0, r1}, bh1[2] = {r2, r3};
                mma_f16(acc[2 * dp + 0], pf, bh0);
                mma_f16(acc[2 * dp + 1], pf, bh1);
            }
        }
    }

    // ---- epilogue: write ctx fp16 ----
    #pragma unroll
    for (int o = 1; o < 4; o <<= 1) {
        lrow0 += __shfl_xor_sync(0xffffffffu, lrow0, o);
        lrow1 += __shfl_xor_sync(0xffffffffu, lrow1, o);
    }
    float inv0 = 1.0f / lrow0, inv1 = 1.0f / lrow1;
    size_t t0 = (size_t)(b * SEQ + q0 + wid * 16 + (lane >> 2));
    size_t t1 = t0 + 8;
    int col = h * HDIM + (lane & 3) * 2;
    #pragma unroll
    for (int dt = 0; dt < 8; dt++) {
        *(uint32_t*)(ctx + t0 * D_MODEL + col + dt * 8) =
            pack2h(acc[dt][0] * inv0, acc[dt][1] * inv0);
        *(uint32_t*)(ctx + t1 * D_MODEL + col + dt * 8) =
            pack2h(acc[dt][2] * inv1, acc[dt][3] * inv1);
    }
}

// ---------------- LayerNorm -> fp16 ----------------
__global__ __launch_bounds__(256) void ln_kernel(const float* __restrict__ x,
                                                 const float* __restrict__ g,
                                                 const float* __restrict__ b,
                                                 __half* __restrict__ oh) {
    int row = blockIdx.x;
    int tid = threadIdx.x;
    const float* xr = x + (size_t)row * D_MODEL;

    float4 xv = *(const float4*)(xr + tid * 4);
    float s  = xv.x + xv.y + xv.z + xv.w;
    float ss = xv.x * xv.x + xv.y * xv.y + xv.z * xv.z + xv.w * xv.w;

    __shared__ float red0[32], red1[32];
    #pragma unroll
    for (int o = 16; o > 0; o >>= 1) {
        s  += __shfl_xor_sync(0xffffffffu, s,  o);
        ss += __shfl_xor_sync(0xffffffffu, ss, o);
    }
    int warp = tid >> 5, lane = tid & 31;
    if (lane == 0) { red0[warp] = s; red1[warp] = ss; }
    __syncthreads();
    if (warp == 0) {
        float a  = (lane < 8) ? red0[lane] : 0.f;
        float a2 = (lane < 8) ? red1[lane] : 0.f;
        #pragma unroll
        for (int o = 4; o > 0; o >>= 1) {
            a  += __shfl_xor_sync(0xffffffffu, a,  o);
            a2 += __shfl_xor_sync(0xffffffffu, a2, o);
        }
        if (lane == 0) { red0[0] = a; red1[0] = a2; }
    }
    __syncthreads();

    float mean = red0[0] * (1.0f / D_MODEL);
    float var  = red1[0] * (1.0f / D_MODEL) - mean * mean;
    float rstd = rsqrtf(var + 1e-5f);

    float4 gv = *(const float4*)(g + tid * 4);
    float4 bv = *(const float4*)(b + tid * 4);
    float o0 = (xv.x - mean) * rstd * gv.x + bv.x;
    float o1 = (xv.y - mean) * rstd * gv.y + bv.y;
    float o2 = (xv.z - mean) * rstd * gv.z + bv.z;
    float o3 = (xv.w - mean) * rstd * gv.w + bv.w;
    *(uint2*)(oh + (size_t)row * D_MODEL + tid * 4) =
        make_uint2(pack2h(o0, o1), pack2h(o2, o3));
}

// ---------------- launch ----------------
extern "C" void kernel_launch(void* const* d_in, const int* in_sizes, int n_in,
                              void* d_out, int out_size) {
    const float* x     = (const float*)d_in[0];
    const float* qkv_w = (const float*)d_in[1];
    const float* qkv_b = (const float*)d_in[2];
    const float* out_w = (const float*)d_in[3];
    const float* out_b = (const float*)d_in[4];
    const float* ff1_w = (const float*)d_in[5];
    const float* ff1_b = (const float*)d_in[6];
    const float* ff2_w = (const float*)d_in[7];
    const float* ff2_b = (const float*)d_in[8];
    const float* ln1_g = (const float*)d_in[9];
    const float* ln1_b = (const float*)d_in[10];
    const float* ln2_g = (const float*)d_in[11];
    const float* ln2_b = (const float*)d_in[12];
    float* out = (float*)d_out;

    __half *h, *qkv, *ctx, *ffh, *wq, *wo, *w1, *w2;
    float* x1;
    cudaGetSymbolAddress((void**)&h,   g_h);
    cudaGetSymbolAddress((void**)&qkv, g_qkv);
    cudaGetSymbolAddress((void**)&ctx, g_ctx);
    cudaGetSymbolAddress((void**)&ffh, g_ffh);
    cudaGetSymbolAddress((void**)&x1,  g_x1);
    cudaGetSymbolAddress((void**)&wq, g_wq);  cudaGetSymbolAddress((void**)&wo, g_wo);
    cudaGetSymbolAddress((void**)&w1, g_w1);  cudaGetSymbolAddress((void**)&w2, g_w2);

    cudaFuncSetAttribute(hmma_gemm<false, false, true>,
                         cudaFuncAttributeMaxDynamicSharedMemorySize, GEMM_SMEM);
    cudaFuncSetAttribute(hmma_gemm<false, true, false>,
                         cudaFuncAttributeMaxDynamicSharedMemorySize, GEMM_SMEM);
    cudaFuncSetAttribute(hmma_gemm<true, false, true>,
                         cudaFuncAttributeMaxDynamicSharedMemorySize, GEMM_SMEM);
    cudaFuncSetAttribute(attn_hmma,
                         cudaFuncAttributeMaxDynamicSharedMemorySize, ATT_SMEM);

    // 0. weight conversion (transpose + fp16)
    wconv<<<dim3(3 * D_MODEL / 32, D_MODEL / 32), 256>>>(qkv_w, wq, 3 * D_MODEL, D_MODEL);
    wconv<<<dim3(D_MODEL / 32, D_MODEL / 32), 256>>>(out_w, wo, D_MODEL, D_MODEL);
    wconv<<<dim3(FFH / 32, D_MODEL / 32), 256>>>(ff1_w, w1, FFH, D_MODEL);
    wconv<<<dim3(D_MODEL / 32, FFH / 32), 256>>>(ff2_w, w2, D_MODEL, FFH);

    // 1. h = LN1(x) -> fp16
    ln_kernel<<<NTOK, 256>>>(x, ln1_g, ln1_b, h);
    // 2. qkv = h @ qkv_w + qkv_b -> fp16
    hmma_gemm<false, false, true><<<dim3(3 * D_MODEL / 128, NTOK / 128), 512, GEMM_SMEM>>>(
        h, wq, qkv_b, nullptr, nullptr, qkv, NTOK, 3 * D_MODEL, D_MODEL);
    // 3. ctx = attention(qkv) -> fp16
    attn_hmma<<<dim3(SEQ / 128, NHEAD, BATCH), 256, ATT_SMEM>>>(qkv, ctx);
    // 4. x1 = ctx @ out_w + out_b + x   (fp32)
    hmma_gemm<false, true, false><<<dim3(D_MODEL / 128, NTOK / 128), 512, GEMM_SMEM>>>(
        ctx, wo, out_b, x, x1, nullptr, NTOK, D_MODEL, D_MODEL);
    // 5. h2 = LN2(x1) -> fp16
    ln_kernel<<<NTOK, 256>>>(x1, ln2_g, ln2_b, h);
    // 6. ffh = gelu(h2 @ ff1_w + ff1_b) -> fp16
    hmma_gemm<true, false, true><<<dim3(FFH / 128, NTOK / 128), 512, GEMM_SMEM>>>(
        h, w1, ff1_b, nullptr, nullptr, ffh, NTOK, FFH, D_MODEL);
    // 7. out = ffh @ ff2_w + ff2_b + x1  (fp32)
    hmma_gemm<false, true, false><<<dim3(D_MODEL / 128, NTOK / 128), 512, GEMM_SMEM>>>(
        ffh, w2, ff2_b, x1, out, nullptr, NTOK, D_MODEL, FFH);
}

// round 13
// speedup vs baseline: 1.4812x; 1.4812x over previous
#include <cuda_runtime.h>
#include <cuda_fp16.h>
#include <math.h>
#include <stdint.h>

#define D_MODEL 1024
#define NHEAD   16
#define HDIM    64
#define FFH     2048
#define BATCH   4
#define SEQ     2048
#define NTOK    (BATCH * SEQ)   // 8192

// ---------------- scratch (alloc-free: __device__ globals) ----------------
__device__ __half g_h[NTOK * D_MODEL];
__device__ __half g_qkv[NTOK * 3 * D_MODEL];
__device__ __half g_ctx[NTOK * D_MODEL];
__device__ float  g_x1[NTOK * D_MODEL];
__device__ __half g_ffh[NTOK * FFH];
// pre-converted transposed weights  Wt[n][k] = fp16(W[k][n])
__device__ __half g_wq[3 * D_MODEL * D_MODEL];
__device__ __half g_wo[D_MODEL * D_MODEL];
__device__ __half g_w1[FFH * D_MODEL];
__device__ __half g_w2[D_MODEL * FFH];

// ======================= helpers =======================
__device__ __forceinline__ uint32_t smem_u32(const void* p) {
    uint32_t a;
    asm("{ .reg .u64 t; cvta.to.shared.u64 t, %1; cvt.u32.u64 %0, t; }" : "=r"(a) : "l"(p));
    return a;
}
__device__ __forceinline__ void cp16(uint32_t d, const void* s) {
    asm volatile("cp.async.cg.shared.global [%0], [%1], 16;" :: "r"(d), "l"(s));
}
__device__ __forceinline__ void cp_commit() {
    asm volatile("cp.async.commit_group;");
}
template <int N>
__device__ __forceinline__ void cp_wait() {
    asm volatile("cp.async.wait_group %0;" :: "n"(N));
}
__device__ __forceinline__ void ldmx4(uint32_t& r0, uint32_t& r1, uint32_t& r2, uint32_t& r3,
                                      uint32_t addr) {
    asm volatile("ldmatrix.sync.aligned.m8n8.x4.shared.b16 {%0,%1,%2,%3}, [%4];"
                 : "=r"(r0), "=r"(r1), "=r"(r2), "=r"(r3) : "r"(addr));
}
__device__ __forceinline__ void ldmx4t(uint32_t& r0, uint32_t& r1, uint32_t& r2, uint32_t& r3,
                                       uint32_t addr) {
    asm volatile("ldmatrix.sync.aligned.m8n8.x4.trans.shared.b16 {%0,%1,%2,%3}, [%4];"
                 : "=r"(r0), "=r"(r1), "=r"(r2), "=r"(r3) : "r"(addr));
}
__device__ __forceinline__ void mma_f16(float* d, const uint32_t* a, const uint32_t* b) {
    asm volatile(
        "mma.sync.aligned.m16n8k16.row.col.f32.f16.f16.f32 "
        "{%0,%1,%2,%3},{%4,%5,%6,%7},{%8,%9},{%0,%1,%2,%3};"
        : "+f"(d[0]), "+f"(d[1]), "+f"(d[2]), "+f"(d[3])
        : "r"(a[0]), "r"(a[1]), "r"(a[2]), "r"(a[3]), "r"(b[0]), "r"(b[1]));
}
__device__ __forceinline__ uint32_t pack2h(float a, float b) {
    __half2 h = __halves2half2(__float2half_rn(a), __float2half_rn(b));
    return *reinterpret_cast<uint32_t*>(&h);
}
__device__ __forceinline__ float gelu_exact(float v) {
    return 0.5f * v * (1.0f + erff(v * 0.70710678118654752f));
}

// ======================= weight transpose + fp16 convert =======================
__global__ __launch_bounds__(256) void wconv(const float* __restrict__ W,
                                             __half* __restrict__ Wh,
                                             int N, int K) {
    __shared__ float t[32][33];
    int n0 = blockIdx.x * 32, k0 = blockIdx.y * 32;
    int tx = threadIdx.x & 31, ty = threadIdx.x >> 5;
    #pragma unroll
    for (int i = ty; i < 32; i += 8)
        t[i][tx] = W[(size_t)(k0 + i) * N + n0 + tx];
    __syncthreads();
    #pragma unroll
    for (int i = ty; i < 32; i += 8)
        Wh[(size_t)(n0 + i) * K + k0 + tx] = __float2half_rn(t[tx][i]);
}

// ======================= HMMA fp16 GEMM =======================
// C = A @ Wt^T + bias (+gelu)(+res); A fp16 [M][K], Wt fp16 [N][K].
// CTA 128x128, BK=32, 512 thr (warp 32x32), 3-stage single-sync pipeline.
#define TPITCH 80
#define TILE_B (128 * TPITCH)          // 10240
#define BUF_B  (2 * TILE_B)            // 20480 (A, B)
#define NSTAGE 3
#define GEMM_SMEM (NSTAGE * BUF_B)     // 61440

template <bool GELU, bool RES, bool OHALF>
__global__ __launch_bounds__(512, 1) void hmma_gemm(const __half* __restrict__ A,
                                                    const __half* __restrict__ Bt,
                                                    const float* __restrict__ bias,
                                                    const float* __restrict__ R,
                                                    float* __restrict__ C,
                                                    __half* __restrict__ Oh,
                                                    int M, int N, int K) {
    extern __shared__ char smem[];
    const uint32_t sb = smem_u32(smem);
    const int tid = threadIdx.x;
    const int lane = tid & 31;
    const int wid = tid >> 5;
    const int wm = wid & 3;
    const int wn = wid >> 2;
    const int m0 = blockIdx.y * 128, n0 = blockIdx.x * 128;

    const int srow = tid >> 2;
    const int sseg = tid & 3;
    const uint32_t sdst = (uint32_t)(srow * TPITCH + sseg * 16);

    float acc[2][4][4];
    #pragma unroll
    for (int i = 0; i < 2; i++)
        #pragma unroll
        for (int j = 0; j < 4; j++)
            #pragma unroll
            for (int l = 0; l < 4; l++) acc[i][j][l] = 0.f;

    const int nch = K >> 5;

    auto stage = [&](int c, int buf) {
        const int k0 = (c << 5) + sseg * 8;
        uint32_t d = sb + buf * BUF_B + sdst;
        cp16(d,          A  + (size_t)(m0 + srow) * K + k0);
        cp16(d + TILE_B, Bt + (size_t)(n0 + srow) * K + k0);
        cp_commit();
    };

    stage(0, 0);
    if (nch > 1) stage(1, 1);

    for (int c = 0; c < nch; c++) {
        if (c + 1 < nch) cp_wait<1>(); else cp_wait<0>();
        __syncthreads();
        if (c + 2 < nch) stage(c + 2, (c + 2) % NSTAGE);

        const uint32_t bufb = sb + (c % NSTAGE) * BUF_B;
        const uint32_t lrow = (lane & 15);
        const uint32_t lseg = (lane >> 4) << 4;
        #pragma unroll
        for (int ks = 0; ks < 2; ks++) {
            const uint32_t kb = ks * 32;
            uint32_t af[2][4], b4[2][4];
            #pragma unroll
            for (int mt = 0; mt < 2; mt++) {
                uint32_t ar = (uint32_t)((wm * 32 + mt * 16 + lrow) * TPITCH) + kb + lseg;
                ldmx4(af[mt][0], af[mt][1], af[mt][2], af[mt][3], bufb + ar);
            }
            #pragma unroll
            for (int np = 0; np < 2; np++) {
                uint32_t br = (uint32_t)((wn * 32 + np * 16 + lrow) * TPITCH) + kb + lseg;
                ldmx4(b4[np][0], b4[np][1], b4[np][2], b4[np][3], bufb + TILE_B + br);
            }
            #pragma unroll
            for (int nt = 0; nt < 4; nt++) {
                const int np = nt >> 1, sel = nt & 1;
                uint32_t bf[2] = {b4[np][sel], b4[np][sel + 2]};
                #pragma unroll
                for (int mt = 0; mt < 2; mt++)
                    mma_f16(acc[mt][nt], af[mt], bf);
            }
        }
    }

    // ---- epilogue ----
    #pragma unroll
    for (int mt = 0; mt < 2; mt++) {
        #pragma unroll
        for (int nt = 0; nt < 4; nt++) {
            int col = n0 + wn * 32 + nt * 8 + (lane & 3) * 2;
            float b0 = bias[col], b1 = bias[col + 1];
            #pragma unroll
            for (int half = 0; half < 2; half++) {
                int row = m0 + wm * 32 + mt * 16 + (lane >> 2) + half * 8;
                float o0 = acc[mt][nt][half * 2 + 0] + b0;
                float o1 = acc[mt][nt][half * 2 + 1] + b1;
                if (GELU) { o0 = gelu_exact(o0); o1 = gelu_exact(o1); }
                if (RES) {
                    const float* rp = R + (size_t)row * N + col;
                    o0 += rp[0]; o1 += rp[1];
                }
                if (OHALF) {
                    *(uint32_t*)(Oh + (size_t)row * N + col) = pack2h(o0, o1);
                } else {
                    *(float2*)(C + (size_t)row * N + col) = make_float2(o0, o1);
                }
            }
        }
    }
}

// ======================= HMMA fp16 flash attention =======================
// Q [128][64] static; K,V triple-buffered cp.async, single sync per tile;
// V loaded with ldmatrix.trans.
#define AP 144
#define AQ 0                            // 128*144 = 18432
#define AKB(b) (18432 + (b) * 9216)     // 3 K buffers
#define AVB(b) (46080 + (b) * 9216)     // 3 V buffers
#define ATT_SMEM 73728

__global__ __launch_bounds__(256, 2) void attn_hmma(const __half* __restrict__ qkv,
                                                    __half* __restrict__ ctx) {
    extern __shared__ char sm[];
    const uint32_t sb = smem_u32(sm);
    const int tid = threadIdx.x;
    const int lane = tid & 31;
    const int wid = tid >> 5;
    const int b = blockIdx.z, h = blockIdx.y;
    const int q0 = blockIdx.x * 128;

    // ---- stage Q [128][64] (plain copies; visible after first barrier) ----
    {
        const size_t qbase = ((size_t)(b * SEQ + q0)) * (3 * D_MODEL) + h * HDIM;
        #pragma unroll
        for (int rep = 0; rep < 4; rep++) {
            int idx = rep * 256 + tid;
            int row = idx >> 3;
            int seg = idx & 7;
            size_t src = qbase + (size_t)row * (3 * D_MODEL) + seg * 8;
            *(uint4*)(sm + AQ + row * AP + seg * 16) = *(const uint4*)(qkv + src);
        }
    }

    auto stage_kv = [&](int kt, int buf) {
        const size_t kbase = ((size_t)(b * SEQ + kt)) * (3 * D_MODEL) + D_MODEL + h * HDIM;
        #pragma unroll
        for (int rep = 0; rep < 2; rep++) {
            int idx = rep * 256 + tid;
            int row = idx >> 3;
            int seg = idx & 7;
            size_t src = kbase + (size_t)row * (3 * D_MODEL) + seg * 8;
            uint32_t dst = (uint32_t)(row * AP + seg * 16);
            cp16(sb + AKB(buf) + dst, qkv + src);
            cp16(sb + AVB(buf) + dst, qkv + src + D_MODEL);
        }
        cp_commit();
    };

    float acc[8][4];
    #pragma unroll
    for (int i = 0; i < 8; i++)
        #pragma unroll
        for (int j = 0; j < 4; j++) acc[i][j] = 0.f;
    float mrow0 = -1e30f, mrow1 = -1e30f;
    float lrow0 = 0.f, lrow1 = 0.f;

    const int NT = SEQ / 64;   // 32
    stage_kv(0, 0);
    stage_kv(64, 1);

    for (int it = 0; it < NT; it++) {
        if (it + 1 < NT) cp_wait<1>(); else cp_wait<0>();
        __syncthreads();
        if (it + 2 < NT) stage_kv((it + 2) * 64, (it + 2) % 3);

        const uint32_t kbb = sb + AKB(it % 3);
        const uint32_t vbb = sb + AVB(it % 3);

        // ---- S = Q @ K^T ----
        float sf[8][4];
        #pragma unroll
        for (int i = 0; i < 8; i++)
            #pragma unroll
            for (int j = 0; j < 4; j++) sf[i][j] = 0.f;

        #pragma unroll
        for (int ks = 0; ks < 4; ks++) {
            uint32_t qaddr = sb + AQ + (uint32_t)((wid * 16 + (lane & 15)) * AP)
                           + ks * 32 + ((lane >> 4) << 4);
            uint32_t qf[4];
            ldmx4(qf[0], qf[1], qf[2], qf[3], qaddr);
            #pragma unroll
            for (int np = 0; np < 4; np++) {
                uint32_t kaddr = kbb + (uint32_t)((np * 16 + (lane & 15)) * AP)
                               + ks * 32 + ((lane >> 4) << 4);
                uint32_t kf[4];
                ldmx4(kf[0], kf[1], kf[2], kf[3], kaddr);
                uint32_t bh0[2] = {kf[0], kf[2]}, bh1[2] = {kf[1], kf[3]};
                mma_f16(sf[2 * np + 0], qf, bh0);
                mma_f16(sf[2 * np + 1], qf, bh1);
            }
        }
        #pragma unroll
        for (int nt = 0; nt < 8; nt++)
            #pragma unroll
            for (int j = 0; j < 4; j++) sf[nt][j] *= 0.125f;

        // ---- online softmax ----
        float tm0 = -1e30f, tm1 = -1e30f;
        #pragma unroll
        for (int nt = 0; nt < 8; nt++) {
            tm0 = fmaxf(tm0, fmaxf(sf[nt][0], sf[nt][1]));
            tm1 = fmaxf(tm1, fmaxf(sf[nt][2], sf[nt][3]));
        }
        #pragma unroll
        for (int o = 1; o < 4; o <<= 1) {
            tm0 = fmaxf(tm0, __shfl_xor_sync(0xffffffffu, tm0, o));
            tm1 = fmaxf(tm1, __shfl_xor_sync(0xffffffffu, tm1, o));
        }
        float mn0 = fmaxf(mrow0, tm0), mn1 = fmaxf(mrow1, tm1);
        float f0 = __expf(mrow0 - mn0), f1 = __expf(mrow1 - mn1);
        mrow0 = mn0; mrow1 = mn1;
        lrow0 *= f0; lrow1 *= f1;
        #pragma unroll
        for (int dt = 0; dt < 8; dt++) {
            acc[dt][0] *= f0; acc[dt][1] *= f0;
            acc[dt][2] *= f1; acc[dt][3] *= f1;
        }
        #pragma unroll
        for (int nt = 0; nt < 8; nt++) {
            sf[nt][0] = __expf(sf[nt][0] - mn0);
            sf[nt][1] = __expf(sf[nt][1] - mn0);
            sf[nt][2] = __expf(sf[nt][2] - mn1);
            sf[nt][3] = __expf(sf[nt][3] - mn1);
            lrow0 += sf[nt][0] + sf[nt][1];
            lrow1 += sf[nt][2] + sf[nt][3];
        }

        // ---- ctx += P @ V  (V in [key][d] layout, trans ldmatrix) ----
        #pragma unroll
        for (int ks = 0; ks < 4; ks++) {
            int nt0 = 2 * ks, nt1 = 2 * ks + 1;
            uint32_t pf[4];
            pf[0] = pack2h(sf[nt0][0], sf[nt0][1]);
            pf[1] = pack2h(sf[nt0][2], sf[nt0][3]);
            pf[2] = pack2h(sf[nt1][0], sf[nt1][1]);
            pf[3] = pack2h(sf[nt1][2], sf[nt1][3]);
            #pragma unroll
            for (int dp = 0; dp < 4; dp++) {
                uint32_t vaddr = vbb + (uint32_t)((ks * 16 + (lane & 15)) * AP)
                               + dp * 32 + ((lane >> 4) << 4);
                uint32_t r0, r1, r2, r3;
                ldmx4t(r0, r1, r2, r3, vaddr);
                uint32_t bh0[2] = {r0, r1}, bh1[2] = {r2, r3};
                mma_f16(acc[2 * dp + 0], pf, bh0);
                mma_f16(acc[2 * dp + 1], pf, bh1);
            }
        }
    }

    // ---- epilogue: write ctx fp16 ----
    #pragma unroll
    for (int o = 1; o < 4; o <<= 1) {
        lrow0 += __shfl_xor_sync(0xffffffffu, lrow0, o);
        lrow1 += __shfl_xor_sync(0xffffffffu, lrow1, o);
    }
    float inv0 = 1.0f / lrow0, inv1 = 1.0f / lrow1;
    size_t t0 = (size_t)(b * SEQ + q0 + wid * 16 + (lane >> 2));
    size_t t1 = t0 + 8;
    int col = h * HDIM + (lane & 3) * 2;
    #pragma unroll
    for (int dt = 0; dt < 8; dt++) {
        *(uint32_t*)(ctx + t0 * D_MODEL + col + dt * 8) =
            pack2h(acc[dt][0] * inv0, acc[dt][1] * inv0);
        *(uint32_t*)(ctx + t1 * D_MODEL + col + dt * 8) =
            pack2h(acc[dt][2] * inv1, acc[dt][3] * inv1);
    }
}

// ---------------- LayerNorm -> fp16 ----------------
__global__ __launch_bounds__(256) void ln_kernel(const float* __restrict__ x,
                                                 const float* __restrict__ g,
                                                 const float* __restrict__ b,
                                                 __half* __restrict__ oh) {
    int row = blockIdx.x;
    int tid = threadIdx.x;
    const float* xr = x + (size_t)row * D_MODEL;

    float4 xv = *(const float4*)(xr + tid * 4);
    float s  = xv.x + xv.y + xv.z + xv.w;
    float ss = xv.x * xv.x + xv.y * xv.y + xv.z * xv.z + xv.w * xv.w;

    __shared__ float red0[32], red1[32];
    #pragma unroll
    for (int o = 16; o > 0; o >>= 1) {
        s  += __shfl_xor_sync(0xffffffffu, s,  o);
        ss += __shfl_xor_sync(0xffffffffu, ss, o);
    }
    int warp = tid >> 5, lane = tid & 31;
    if (lane == 0) { red0[warp] = s; red1[warp] = ss; }
    __syncthreads();
    if (warp == 0) {
        float a  = (lane < 8) ? red0[lane] : 0.f;
        float a2 = (lane < 8) ? red1[lane] : 0.f;
        #pragma unroll
        for (int o = 4; o > 0; o >>= 1) {
            a  += __shfl_xor_sync(0xffffffffu, a,  o);
            a2 += __shfl_xor_sync(0xffffffffu, a2, o);
        }
        if (lane == 0) { red0[0] = a; red1[0] = a2; }
    }
    __syncthreads();

    float mean = red0[0] * (1.0f / D_MODEL);
    float var  = red1[0] * (1.0f / D_MODEL) - mean * mean;
    float rstd = rsqrtf(var + 1e-5f);

    float4 gv = *(const float4*)(g + tid * 4);
    float4 bv = *(const float4*)(b + tid * 4);
    float o0 = (xv.x - mean) * rstd * gv.x + bv.x;
    float o1 = (xv.y - mean) * rstd * gv.y + bv.y;
    float o2 = (xv.z - mean) * rstd * gv.z + bv.z;
    float o3 = (xv.w - mean) * rstd * gv.w + bv.w;
    *(uint2*)(oh + (size_t)row * D_MODEL + tid * 4) =
        make_uint2(pack2h(o0, o1), pack2h(o2, o3));
}

// ---------------- launch ----------------
extern "C" void kernel_launch(void* const* d_in, const int* in_sizes, int n_in,
                              void* d_out, int out_size) {
    const float* x     = (const float*)d_in[0];
    const float* qkv_w = (const float*)d_in[1];
    const float* qkv_b = (const float*)d_in[2];
    const float* out_w = (const float*)d_in[3];
    const float* out_b = (const float*)d_in[4];
    const float* ff1_w = (const float*)d_in[5];
    const float* ff1_b = (const float*)d_in[6];
    const float* ff2_w = (const float*)d_in[7];
    const float* ff2_b = (const float*)d_in[8];
    const float* ln1_g = (const float*)d_in[9];
    const float* ln1_b = (const float*)d_in[10];
    const float* ln2_g = (const float*)d_in[11];
    const float* ln2_b = (const float*)d_in[12];
    float* out = (float*)d_out;

    __half *h, *qkv, *ctx, *ffh, *wq, *wo, *w1, *w2;
    float* x1;
    cudaGetSymbolAddress((void**)&h,   g_h);
    cudaGetSymbolAddress((void**)&qkv, g_qkv);
    cudaGetSymbolAddress((void**)&ctx, g_ctx);
    cudaGetSymbolAddress((void**)&ffh, g_ffh);
    cudaGetSymbolAddress((void**)&x1,  g_x1);
    cudaGetSymbolAddress((void**)&wq, g_wq);  cudaGetSymbolAddress((void**)&wo, g_wo);
    cudaGetSymbolAddress((void**)&w1, g_w1);  cudaGetSymbolAddress((void**)&w2, g_w2);

    cudaFuncSetAttribute(hmma_gemm<false, false, true>,
                         cudaFuncAttributeMaxDynamicSharedMemorySize, GEMM_SMEM);
    cudaFuncSetAttribute(hmma_gemm<false, true, false>,
                         cudaFuncAttributeMaxDynamicSharedMemorySize, GEMM_SMEM);
    cudaFuncSetAttribute(hmma_gemm<true, false, true>,
                         cudaFuncAttributeMaxDynamicSharedMemorySize, GEMM_SMEM);
    cudaFuncSetAttribute(attn_hmma,
                         cudaFuncAttributeMaxDynamicSharedMemorySize, ATT_SMEM);

    // 0. weight conversion (transpose + fp16)
    wconv<<<dim3(3 * D_MODEL / 32, D_MODEL / 32), 256>>>(qkv_w, wq, 3 * D_MODEL, D_MODEL);
    wconv<<<dim3(D_MODEL / 32, D_MODEL / 32), 256>>>(out_w, wo, D_MODEL, D_MODEL);
    wconv<<<dim3(FFH / 32, D_MODEL / 32), 256>>>(ff1_w, w1, FFH, D_MODEL);
    wconv<<<dim3(D_MODEL / 32, FFH / 32), 256>>>(ff2_w, w2, D_MODEL, FFH);

    // 1. h = LN1(x) -> fp16
    ln_kernel<<<NTOK, 256>>>(x, ln1_g, ln1_b, h);
    // 2. qkv = h @ qkv_w + qkv_b -> fp16
    hmma_gemm<false, false, true><<<dim3(3 * D_MODEL / 128, NTOK / 128), 512, GEMM_SMEM>>>(
        h, wq, qkv_b, nullptr, nullptr, qkv, NTOK, 3 * D_MODEL, D_MODEL);
    // 3. ctx = attention(qkv) -> fp16
    attn_hmma<<<dim3(SEQ / 128, NHEAD, BATCH), 256, ATT_SMEM>>>(qkv, ctx);
    // 4. x1 = ctx @ out_w + out_b + x   (fp32)
    hmma_gemm<false, true, false><<<dim3(D_MODEL / 128, NTOK / 128), 512, GEMM_SMEM>>>(
        ctx, wo, out_b, x, x1, nullptr, NTOK, D_MODEL, D_MODEL);
    // 5. h2 = LN2(x1) -> fp16
    ln_kernel<<<NTOK, 256>>>(x1, ln2_g, ln2_b, h);
    // 6. ffh = gelu(h2 @ ff1_w + ff1_b) -> fp16
    hmma_gemm<true, false, true><<<dim3(FFH / 128, NTOK / 128), 512, GEMM_SMEM>>>(
        h, w1, ff1_b, nullptr, nullptr, ffh, NTOK, FFH, D_MODEL);
    // 7. out = ffh @ ff2_w + ff2_b + x1  (fp32)
    hmma_gemm<false, true, false><<<dim3(D_MODEL / 128, NTOK / 128), 512, GEMM_SMEM>>>(
        ffh, w2, ff2_b, x1, out, nullptr, NTOK, D_MODEL, FFH);
}